// round 14
// baseline (speedup 1.0000x reference)
#include <cuda_runtime.h>
#include <cuda_bf16.h>
#include <cstdint>

// Problem: B=4, S=1024, HID=1024, H=16, DH=64
// inputs: 0 hidden [4096,1024] f32, 1 mask [4,1024] f32, 2 freqs [1024,64] f32,
//         3 Wq, 4 bq, 5 Wk, 6 bk, 7 Wv, 8 bv
// output: ctx [4,1024,1024] f32

#define BATCH 4
#define SEQ   1024
#define HID   1024
#define NH    16
#define DH    64

// scratch
__device__ float    g_q [BATCH*NH*SEQ*DH];   // f32 row-major (pre-rope)
__device__ uint32_t g_q2[BATCH*NH*SEQ*DH];   // tf32 bits, A-frag-major (post-rope)
__device__ float    g_k [BATCH*NH*SEQ*DH];   // f32 row-major (pre-rope)
__device__ uint32_t g_k2[BATCH*NH*SEQ*DH];   // tf32 bits, B-frag pair-major (post-rope)
__device__ uint32_t g_v [BATCH*NH*SEQ*DH];   // tf32 bits, B-frag pair-major
__device__ uint32_t g_xt[BATCH*SEQ*HID];     // X tf32 bits, A-fragment-major
__device__ uint32_t g_wc[3*HID*HID];         // W tf32 bits, B-fragment pair-major

__device__ __forceinline__ uint32_t f32_to_tf32(float x) {
    uint32_t u;
    asm("cvt.rna.tf32.f32 %0, %1;" : "=r"(u) : "f"(x));
    return u;
}

__device__ __forceinline__ void mma_tf32_16x8x8(
    float& c0, float& c1, float& c2, float& c3,
    uint32_t a0, uint32_t a1, uint32_t a2, uint32_t a3,
    uint32_t b0, uint32_t b1)
{
    asm volatile(
        "mma.sync.aligned.m16n8k8.row.col.f32.tf32.tf32.f32 "
        "{%0,%1,%2,%3}, {%4,%5,%6,%7}, {%8,%9}, {%0,%1,%2,%3};"
        : "+f"(c0), "+f"(c1), "+f"(c2), "+f"(c3)
        : "r"(a0), "r"(a1), "r"(a2), "r"(a3), "r"(b0), "r"(b1));
}

__device__ __forceinline__ uint32_t smem_u32(const void* p) {
    uint32_t a;
    asm("{ .reg .u64 t; cvta.to.shared.u64 t, %1; cvt.u32.u64 %0, t; }" : "=r"(a) : "l"(p));
    return a;
}

#define CP_ASYNC16(dst, src) \
    asm volatile("cp.async.cg.shared.global [%0], [%1], 16;" :: "r"(dst), "l"(src) : "memory")
#define CP_COMMIT() asm volatile("cp.async.commit_group;" ::: "memory")
#define CP_WAIT1()  asm volatile("cp.async.wait_group 1;" ::: "memory")
#define CP_WAIT2()  asm volatile("cp.async.wait_group 2;" ::: "memory")

// ---------------------------------------------------------------------------
// precvt: X -> g_xt (A-fragment-major), W -> g_wc (B-fragment pair-major).
// ---------------------------------------------------------------------------
#define NA_LANES (256*128*32)   // 1048576
#define NB_LANES (128*128*32)   // 524288

__global__ __launch_bounds__(256) void precvt(
    const float* __restrict__ X,
    const float* __restrict__ Wq, const float* __restrict__ Wk, const float* __restrict__ Wv)
{
    size_t g = (size_t)blockIdx.x * 256 + threadIdx.x;
    if (g < NA_LANES) {
        const int lane = (int)(g & 31);
        const int fA   = (int)(g >> 5);
        const int m16 = fA >> 7, k8 = fA & 127;
        const int lr = lane >> 2, lc = lane & 3;
        const int r0 = m16 * 16 + lr, c0 = k8 * 8 + lc;
        uint4 t;
        t.x = f32_to_tf32(X[(size_t)r0 * HID + c0]);
        t.y = f32_to_tf32(X[(size_t)(r0 + 8) * HID + c0]);
        t.z = f32_to_tf32(X[(size_t)r0 * HID + c0 + 4]);
        t.w = f32_to_tf32(X[(size_t)(r0 + 8) * HID + c0 + 4]);
        ((uint4*)g_xt)[g] = t;
    } else {
        g -= NA_LANES;
        const int which = (int)(g / NB_LANES);
        const size_t gg = g % NB_LANES;
        const float* __restrict__ W = (which == 0) ? Wq : (which == 1) ? Wk : Wv;
        const int lane = (int)(gg & 31);
        const int fB   = (int)(gg >> 5);
        const int n8 = fB >> 7, k8 = fB & 127;
        const int lr = lane >> 2, lc = lane & 3;
        const int kk = k8 * 8 + lc, nn = n8 * 8 + lr;
        uint2 t;
        t.x = f32_to_tf32(W[(size_t)kk * HID + nn]);
        t.y = f32_to_tf32(W[(size_t)(kk + 4) * HID + nn]);
        ((uint2*)g_wc)[(size_t)which * NB_LANES + gg] = t;
    }
}

// ---------------------------------------------------------------------------
// QKV projection: CTA 128x256, warp tile 64x64 (8 warps, 2m x 4n), BK=32,
// cp.async 3-stage pipeline, 1 CTA/SM (regs ~190, smem 144KB).
// Each B-frag LDS.64 feeds 4 mt-MMAs; barriers per MMA halved vs R12.
// ---------------------------------------------------------------------------
#define NCH 32
#define A_TILE_B 16384          // 32 A-frags * 512B
#define B_TILE_B 32768          // 128 B-frags * 256B
#define STG_B (A_TILE_B + B_TILE_B)
#define QKV_SMEM (3 * STG_B)    // 147456

__global__ __launch_bounds__(256, 1) void qkv_mma(
    const float* __restrict__ bq, const float* __restrict__ bk, const float* __restrict__ bv)
{
    extern __shared__ uint32_t smw[];
    const uint32_t sb = smem_u32(smw);

    const int which = blockIdx.z;
    const float* __restrict__ bias = (which == 0) ? bq : (which == 1) ? bk : bv;
    const size_t wcoff = (size_t)which * HID * HID * 4;

    const int m0 = blockIdx.y * 128;
    const int n0 = blockIdx.x * 256;
    const int m16_0 = blockIdx.y * 8;
    const int n8_0  = blockIdx.x * 32;

    const int tid  = threadIdx.x;
    const int wid  = tid >> 5;
    const int lane = tid & 31;
    const int lr = lane >> 2;
    const int lc = lane & 3;

    auto issue_stage = [&](int stg, int c) {
        const uint32_t ab = sb + (uint32_t)(stg * STG_B);
        const uint32_t bb = ab + A_TILE_B;
        const int k8_0 = c * 4;
        #pragma unroll
        for (int i = 0; i < 4; i++) {         // A: 32 frags x 512B
            const int f = (tid >> 5) + i * 8;
            const size_t src = ((size_t)((m16_0 + (f >> 2)) * 128 + k8_0 + (f & 3))) * 512
                               + (tid & 31) * 16;
            CP_ASYNC16(ab + (uint32_t)(f * 512 + (tid & 31) * 16),
                       (const char*)g_xt + src);
        }
        #pragma unroll
        for (int i = 0; i < 8; i++) {         // B: 128 frags x 256B
            const int ch = tid + i * 256;
            const int frag = ch >> 4, off = ch & 15;
            const size_t src = ((size_t)((n8_0 + (frag >> 2)) * 128 + k8_0 + (frag & 3))) * 256
                               + off * 16 + wcoff;
            CP_ASYNC16(bb + (uint32_t)(frag * 256 + off * 16),
                       (const char*)g_wc + src);
        }
    };

    float acc[4][8][4];
    #pragma unroll
    for (int mt = 0; mt < 4; mt++)
        #pragma unroll
        for (int nt = 0; nt < 8; nt++)
            #pragma unroll
            for (int r = 0; r < 4; r++) acc[mt][nt][r] = 0.0f;

    issue_stage(0, 0);   CP_COMMIT();
    issue_stage(1, 1);   CP_COMMIT();

    int stg = 0;
    for (int c = 0; c < NCH; c++) {
        CP_WAIT1();
        __syncthreads();

        if (c + 2 < NCH)
            issue_stage((stg + 2) % 3, c + 2);
        CP_COMMIT();

        const uint32_t* As = smw + stg * (STG_B / 4);
        const uint32_t* Bs = As + A_TILE_B / 4;

        #pragma unroll
        for (int kk8 = 0; kk8 < 4; kk8++) {
            uint2 bf[8];
            #pragma unroll
            for (int nt = 0; nt < 8; nt++) {
                const int slot = (((wid >> 1) * 8 + nt) * 4 + kk8);
                bf[nt] = *(const uint2*)(Bs + slot * 64 + lane * 2);
            }
            #pragma unroll
            for (int mt = 0; mt < 4; mt++) {
                const int slot = (((wid & 1) * 4 + mt) * 4 + kk8);
                const uint4 av = *(const uint4*)(As + slot * 128 + lane * 4);
                #pragma unroll
                for (int nt = 0; nt < 8; nt++)
                    mma_tf32_16x8x8(acc[mt][nt][0], acc[mt][nt][1],
                                    acc[mt][nt][2], acc[mt][nt][3],
                                    av.x, av.y, av.z, av.w, bf[nt].x, bf[nt].y);
            }
        }
        stg = (stg + 1) % 3;
    }

    // epilogue: bias + permute. Q,K -> f32 row-major (rope relayouts),
    // V -> tf32 bits in B-fragment pair-major layout.
    const int wm = (wid & 1) * 64;
    const int wn = (wid >> 1) * 64;
    #pragma unroll
    for (int mt = 0; mt < 4; mt++) {
        #pragma unroll
        for (int nt = 0; nt < 8; nt++) {
            const int dd = wn + nt * 8 + 2 * lc;
            const int h  = (n0 + dd) >> 6;
            const int d  = dd & 63;
            const float bx = bias[n0 + dd];
            const float by = bias[n0 + dd + 1];
            #pragma unroll
            for (int half = 0; half < 2; half++) {
                const int m  = m0 + wm + mt * 16 + half * 8 + lr;
                const int b_ = m >> 10;
                const int s  = m & 1023;
                const float ox = acc[mt][nt][2 * half + 0] + bx;
                const float oy = acc[mt][nt][2 * half + 1] + by;
                if (which == 0) {
                    const size_t idx = (((size_t)(b_ * NH + h) * SEQ + s) << 6) + d;
                    *(float2*)&g_q[idx] = make_float2(ox, oy);
                } else if (which == 1) {
                    const size_t idx = (((size_t)(b_ * NH + h) * SEQ + s) << 6) + d;
                    *(float2*)&g_k[idx] = make_float2(ox, oy);
                } else {
                    const size_t fragbase =
                        (((size_t)(b_ * NH + h) * 128 + (s >> 3)) * 8 + (d >> 3)) * 64;
                    const int hw = (s >> 2) & 1;
                    g_v[fragbase + (((d & 7)    ) * 4 + (s & 3)) * 2 + hw] = f32_to_tf32(ox);
                    g_v[fragbase + (((d & 7) + 1) * 4 + (s & 3)) * 2 + hw] = f32_to_tf32(oy);
                }
            }
        }
    }
}

// ---------------------------------------------------------------------------
// RoPE. Q -> tf32 A-frag-major (g_q2); K -> tf32 B-frag pair-major (g_k2).
// ---------------------------------------------------------------------------
__global__ __launch_bounds__(256) void rope_kernel(const float* __restrict__ freqs)
{
    const int p  = blockIdx.x * 256 + threadIdx.x;
    const int d  = p & 31;
    const int s  = (p >> 5) & 1023;
    const int bh = p >> 15;
    const float f = freqs[s * 64 + d];
    const float sn = sinf(f), c = cosf(f);
    const size_t base = (((size_t)bh << 10) + s) * 64 + d;
    if (blockIdx.y == 0) {
        const float x1 = g_q[base];
        const float x2 = g_q[base + 32];
        const uint32_t v1 = f32_to_tf32(x1 * c - x2 * sn);
        const uint32_t v2 = f32_to_tf32(x2 * c + x1 * sn);
        const size_t fb = ((size_t)bh * 64 + (s >> 4)) * 8;
        const int lanew = ((s & 7) * 4 + (d & 3)) * 4 + ((s >> 3) & 1) + 2 * ((d >> 2) & 1);
        g_q2[(fb + (d >> 3)    ) * 128 + lanew] = v1;
        g_q2[(fb + (d >> 3) + 4) * 128 + lanew] = v2;
    } else {
        const float x1 = g_k[base];
        const float x2 = g_k[base + 32];
        const uint32_t v1 = f32_to_tf32(x1 * c - x2 * sn);
        const uint32_t v2 = f32_to_tf32(x2 * c + x1 * sn);
        const size_t slotbase = ((size_t)bh * 128 + (s >> 3)) * 8;
        const int lanepart = (s & 7) * 4 + (d & 3);
        const int halfw    = (d >> 2) & 1;
        g_k2[(slotbase + (d >> 3)    ) * 64 + lanepart * 2 + halfw] = v1;
        g_k2[(slotbase + (d >> 3) + 4) * 64 + lanepart * 2 + halfw] = v2;
    }
}

// ---------------------------------------------------------------------------
// Flash attention (exact R12 version): 1-term tf32, q-tile 64, 4 warps,
// Q via LDG.128 (A-frag-major), K/V fragment-major smem (LDS.64),
// K double-buffered + V single-buffered cp.async, 3 CTAs/SM.
// ---------------------------------------------------------------------------
#define KSTR 68
#define KTILE_W 4096                       // 64 frags * 64 words
#define K0_OFF 0
#define K1_OFF KTILE_W
#define V_OFF  (2 * KTILE_W)               // 8192
#define PS_OFF (V_OFF + KTILE_W)           // 12288
#define MSK_OFF (PS_OFF + 64 * KSTR)       // 16640
#define ATTN_SMEM ((MSK_OFF + SEQ) * 4)    // 70656 bytes -> 3 CTAs/SM

__global__ __launch_bounds__(128, 3) void attn_mma(
    const float* __restrict__ mask, float* __restrict__ out)
{
    extern __shared__ uint32_t sm[];
    const uint32_t sb = smem_u32(sm);
    float*    Msk = (float*)(sm + MSK_OFF);
    uint32_t* Psb = sm + PS_OFF;

    const int q0 = blockIdx.x * 64;
    const int h  = blockIdx.y;
    const int b  = blockIdx.z;
    const int tid  = threadIdx.x;
    const int w    = tid >> 5;
    const int lane = tid & 31;
    const int lr = lane >> 2;
    const int lc = lane & 3;
    const int bh = b * NH + h;

    for (int i = tid; i < SEQ; i += 128) Msk[i] = mask[b * SEQ + i];

    // Q fragments: one LDG.128 per ds, loaded once (A-frag-major)
    uint32_t qh[8][4];
    {
        const uint32_t* qsrc = g_q2 + ((size_t)bh * 64 + (q0 >> 4) + w) * 1024;
        #pragma unroll
        for (int ds = 0; ds < 8; ds++) {
            const uint4 v = *(const uint4*)(qsrc + ds * 128 + lane * 4);
            qh[ds][0] = v.x; qh[ds][1] = v.y; qh[ds][2] = v.z; qh[ds][3] = v.w;
        }
    }
    __syncthreads();

    int nlive = 0;
    while (nlive < 16 && Msk[nlive * 64] >= -1e5f) nlive++;

    auto stage_k = [&](int stg, int kc0) {
        const uint32_t kb = sb + (uint32_t)((stg ? K1_OFF : K0_OFF) * 4);
        const char* src = (const char*)g_k2 + (((size_t)bh * 128 + (kc0 >> 3)) * 2048);
        #pragma unroll
        for (int j = 0; j < 8; j++) {
            const int off = (tid + j * 128) * 16;
            CP_ASYNC16(kb + (uint32_t)off, src + off);
        }
    };
    auto stage_v = [&](int kc0) {
        const uint32_t vb = sb + (uint32_t)(V_OFF * 4);
        const char* src = (const char*)g_v + (((size_t)bh * 128 + (kc0 >> 3)) * 2048);
        #pragma unroll
        for (int j = 0; j < 8; j++) {
            const int off = (tid + j * 128) * 16;
            CP_ASYNC16(vb + (uint32_t)off, src + off);
        }
    };

    float m0 = -1e30f, m1 = -1e30f, l0 = 0.0f, l1 = 0.0f;
    float ctx[8][4];
    #pragma unroll
    for (int nt = 0; nt < 8; nt++)
        #pragma unroll
        for (int r = 0; r < 4; r++) ctx[nt][r] = 0.0f;

    stage_k(0, 0);
    CP_COMMIT();                          // pending: [K0]

    for (int kt = 0; kt < nlive; kt++) {
        const int kc0 = kt * 64;

        stage_v(kc0);
        CP_COMMIT();                      // +[V(kt)]
        if (kt + 1 < nlive)
            stage_k((kt + 1) & 1, kc0 + 64);
        CP_COMMIT();                      // +[K(kt+1)] (possibly empty)

        CP_WAIT2();                       // K(kt) complete
        __syncthreads();

        const uint32_t* Ksb = sm + ((kt & 1) ? K1_OFF : K0_OFF);

        // ---- S = Q K^T (1-term) ----
        float sa[8][4];
        #pragma unroll
        for (int nt = 0; nt < 8; nt++)
            #pragma unroll
            for (int r = 0; r < 4; r++) sa[nt][r] = 0.0f;

        #pragma unroll
        for (int ds = 0; ds < 8; ds++) {
            #pragma unroll
            for (int nt = 0; nt < 8; nt++) {
                const uint2 kv = *(const uint2*)(Ksb + (nt * 8 + ds) * 64 + lane * 2);
                mma_tf32_16x8x8(sa[nt][0], sa[nt][1], sa[nt][2], sa[nt][3],
                                qh[ds][0], qh[ds][1], qh[ds][2], qh[ds][3], kv.x, kv.y);
            }
        }

        // ---- scale + mask + online softmax ----
        float mx0 = -1e30f, mx1 = -1e30f;
        #pragma unroll
        for (int nt = 0; nt < 8; nt++) {
            const float mk0 = Msk[kc0 + nt * 8 + 2 * lc    ];
            const float mk1 = Msk[kc0 + nt * 8 + 2 * lc + 1];
            sa[nt][0] = fmaf(sa[nt][0], 0.125f, mk0);
            sa[nt][1] = fmaf(sa[nt][1], 0.125f, mk1);
            sa[nt][2] = fmaf(sa[nt][2], 0.125f, mk0);
            sa[nt][3] = fmaf(sa[nt][3], 0.125f, mk1);
            mx0 = fmaxf(mx0, fmaxf(sa[nt][0], sa[nt][1]));
            mx1 = fmaxf(mx1, fmaxf(sa[nt][2], sa[nt][3]));
        }
        mx0 = fmaxf(mx0, __shfl_xor_sync(0xffffffffu, mx0, 1));
        mx0 = fmaxf(mx0, __shfl_xor_sync(0xffffffffu, mx0, 2));
        mx1 = fmaxf(mx1, __shfl_xor_sync(0xffffffffu, mx1, 1));
        mx1 = fmaxf(mx1, __shfl_xor_sync(0xffffffffu, mx1, 2));

        const float mn0 = fmaxf(m0, mx0);
        const float mn1 = fmaxf(m1, mx1);
        const float cr0 = __expf(m0 - mn0);
        const float cr1 = __expf(m1 - mn1);
        l0 *= cr0; l1 *= cr1;
        m0 = mn0; m1 = mn1;

        float ps0 = 0.0f, ps1 = 0.0f;
        #pragma unroll
        for (int nt = 0; nt < 8; nt++) {
            ctx[nt][0] *= cr0; ctx[nt][1] *= cr0;
            ctx[nt][2] *= cr1; ctx[nt][3] *= cr1;
            sa[nt][0] = __expf(sa[nt][0] - mn0);
            sa[nt][1] = __expf(sa[nt][1] - mn0);
            sa[nt][2] = __expf(sa[nt][2] - mn1);
            sa[nt][3] = __expf(sa[nt][3] - mn1);
            ps0 += sa[nt][0] + sa[nt][1];
            ps1 += sa[nt][2] + sa[nt][3];
        }
        ps0 += __shfl_xor_sync(0xffffffffu, ps0, 1);
        ps0 += __shfl_xor_sync(0xffffffffu, ps0, 2);
        ps1 += __shfl_xor_sync(0xffffffffu, ps1, 1);
        ps1 += __shfl_xor_sync(0xffffffffu, ps1, 2);
        l0 += ps0; l1 += ps1;

        // store P as tf32 bits (warp-private rows)
        #pragma unroll
        for (int nt = 0; nt < 8; nt++) {
            uint2 u0, u1;
            u0.x = f32_to_tf32(sa[nt][0]); u0.y = f32_to_tf32(sa[nt][1]);
            u1.x = f32_to_tf32(sa[nt][2]); u1.y = f32_to_tf32(sa[nt][3]);
            *(uint2*)&Psb[(16 * w + lr    ) * KSTR + nt * 8 + 2 * lc] = u0;
            *(uint2*)&Psb[(16 * w + lr + 8) * KSTR + nt * 8 + 2 * lc] = u1;
        }
        __syncwarp();

        CP_WAIT1();                       // V(kt) complete
        __syncthreads();

        const uint32_t* Vsb = sm + V_OFF;

        // ---- ctx += P V (1-term, V fragment-major LDS.64) ----
        #pragma unroll
        for (int kk = 0; kk < 8; kk++) {
            uint32_t ah[4];
            ah[0] = Psb[(16 * w + lr    ) * KSTR + kk * 8 + lc    ];
            ah[1] = Psb[(16 * w + lr + 8) * KSTR + kk * 8 + lc    ];
            ah[2] = Psb[(16 * w + lr    ) * KSTR + kk * 8 + lc + 4];
            ah[3] = Psb[(16 * w + lr + 8) * KSTR + kk * 8 + lc + 4];
            #pragma unroll
            for (int nt = 0; nt < 8; nt++) {
                const uint2 vv = *(const uint2*)(Vsb + (kk * 8 + nt) * 64 + lane * 2);
                mma_tf32_16x8x8(ctx[nt][0], ctx[nt][1], ctx[nt][2], ctx[nt][3],
                                ah[0], ah[1], ah[2], ah[3], vv.x, vv.y);
            }
        }

        __syncthreads();                  // all warps done with V before refill
    }

    const float inv0 = 1.0f / l0;
    const float inv1 = 1.0f / l1;
    const int row0 = q0 + 16 * w + lr;
    const int row1 = row0 + 8;
    #pragma unroll
    for (int nt = 0; nt < 8; nt++) {
        const int d = nt * 8 + 2 * lc;
        *(float2*)&out[(size_t)(b * SEQ + row0) * (NH * DH) + h * 64 + d] =
            make_float2(ctx[nt][0] * inv0, ctx[nt][1] * inv0);
        *(float2*)&out[(size_t)(b * SEQ + row1) * (NH * DH) + h * 64 + d] =
            make_float2(ctx[nt][2] * inv1, ctx[nt][3] * inv1);
    }
}

// ---------------------------------------------------------------------------
extern "C" void kernel_launch(void* const* d_in, const int* in_sizes, int n_in,
                              void* d_out, int out_size)
{
    const float* X     = (const float*)d_in[0];
    const float* mask  = (const float*)d_in[1];
    const float* freqs = (const float*)d_in[2];
    const float* Wq    = (const float*)d_in[3];
    const float* bq    = (const float*)d_in[4];
    const float* Wk    = (const float*)d_in[5];
    const float* bk    = (const float*)d_in[6];
    const float* Wv    = (const float*)d_in[7];
    const float* bv    = (const float*)d_in[8];
    float* out = (float*)d_out;

    cudaFuncSetAttribute(qkv_mma,  cudaFuncAttributeMaxDynamicSharedMemorySize, QKV_SMEM);
    cudaFuncSetAttribute(attn_mma, cudaFuncAttributeMaxDynamicSharedMemorySize, ATTN_SMEM);

    const int total = NA_LANES + 3 * NB_LANES;
    precvt<<<total / 256, 256>>>(X, Wq, Wk, Wv);

    dim3 gG(HID / 256, (BATCH * SEQ) / 128, 3);   // 4 x 32 x 3 = 384 CTAs
    qkv_mma<<<gG, 256, QKV_SMEM>>>(bq, bk, bv);

    dim3 gR((BATCH * NH * SEQ * 32) / 256, 2);
    rope_kernel<<<gR, 256>>>(freqs);

    dim3 gA(SEQ / 64, NH, BATCH);                 // 16 x 16 x 4
    attn_mma<<<gA, 128, ATTN_SMEM>>>(mask, out);
}

// round 16
// speedup vs baseline: 1.0235x; 1.0235x over previous
#include <cuda_runtime.h>
#include <cuda_bf16.h>
#include <cstdint>

// Problem: B=4, S=1024, HID=1024, H=16, DH=64
// inputs: 0 hidden [4096,1024] f32, 1 mask [4,1024] f32, 2 freqs [1024,64] f32,
//         3 Wq, 4 bq, 5 Wk, 6 bk, 7 Wv, 8 bv
// output: ctx [4,1024,1024] f32

#define BATCH 4
#define SEQ   1024
#define HID   1024
#define NH    16
#define DH    64

// scratch
__device__ float    g_q [BATCH*NH*SEQ*DH];   // f32 row-major (pre-rope)
__device__ uint32_t g_q2[BATCH*NH*SEQ*DH];   // tf32 bits, A-frag-major (post-rope)
__device__ float    g_k [BATCH*NH*SEQ*DH];   // f32 row-major (pre-rope)
__device__ uint32_t g_k2[BATCH*NH*SEQ*DH];   // tf32 bits, B-frag pair-major (post-rope)
__device__ uint32_t g_v [BATCH*NH*SEQ*DH];   // tf32 bits, B-frag pair-major
__device__ uint32_t g_xt[BATCH*SEQ*HID];     // X tf32 bits, A-fragment-major
__device__ uint32_t g_wc[3*HID*HID];         // W tf32 bits, B-fragment pair-major

__device__ __forceinline__ uint32_t f32_to_tf32(float x) {
    uint32_t u;
    asm("cvt.rna.tf32.f32 %0, %1;" : "=r"(u) : "f"(x));
    return u;
}

__device__ __forceinline__ void mma_tf32_16x8x8(
    float& c0, float& c1, float& c2, float& c3,
    uint32_t a0, uint32_t a1, uint32_t a2, uint32_t a3,
    uint32_t b0, uint32_t b1)
{
    asm volatile(
        "mma.sync.aligned.m16n8k8.row.col.f32.tf32.tf32.f32 "
        "{%0,%1,%2,%3}, {%4,%5,%6,%7}, {%8,%9}, {%0,%1,%2,%3};"
        : "+f"(c0), "+f"(c1), "+f"(c2), "+f"(c3)
        : "r"(a0), "r"(a1), "r"(a2), "r"(a3), "r"(b0), "r"(b1));
}

__device__ __forceinline__ uint32_t smem_u32(const void* p) {
    uint32_t a;
    asm("{ .reg .u64 t; cvta.to.shared.u64 t, %1; cvt.u32.u64 %0, t; }" : "=r"(a) : "l"(p));
    return a;
}

#define CP_ASYNC16(dst, src) \
    asm volatile("cp.async.cg.shared.global [%0], [%1], 16;" :: "r"(dst), "l"(src) : "memory")
#define CP_COMMIT() asm volatile("cp.async.commit_group;" ::: "memory")
#define CP_WAIT1()  asm volatile("cp.async.wait_group 1;" ::: "memory")

// ---------------------------------------------------------------------------
// precvt: X -> g_xt (A-fragment-major), W -> g_wc (B-fragment pair-major).
// ---------------------------------------------------------------------------
#define NA_LANES (256*128*32)   // 1048576
#define NB_LANES (128*128*32)   // 524288

__global__ __launch_bounds__(256) void precvt(
    const float* __restrict__ X,
    const float* __restrict__ Wq, const float* __restrict__ Wk, const float* __restrict__ Wv)
{
    size_t g = (size_t)blockIdx.x * 256 + threadIdx.x;
    if (g < NA_LANES) {
        const int lane = (int)(g & 31);
        const int fA   = (int)(g >> 5);
        const int m16 = fA >> 7, k8 = fA & 127;
        const int lr = lane >> 2, lc = lane & 3;
        const int r0 = m16 * 16 + lr, c0 = k8 * 8 + lc;
        uint4 t;
        t.x = f32_to_tf32(X[(size_t)r0 * HID + c0]);
        t.y = f32_to_tf32(X[(size_t)(r0 + 8) * HID + c0]);
        t.z = f32_to_tf32(X[(size_t)r0 * HID + c0 + 4]);
        t.w = f32_to_tf32(X[(size_t)(r0 + 8) * HID + c0 + 4]);
        ((uint4*)g_xt)[g] = t;
    } else {
        g -= NA_LANES;
        const int which = (int)(g / NB_LANES);
        const size_t gg = g % NB_LANES;
        const float* __restrict__ W = (which == 0) ? Wq : (which == 1) ? Wk : Wv;
        const int lane = (int)(gg & 31);
        const int fB   = (int)(gg >> 5);
        const int n8 = fB >> 7, k8 = fB & 127;
        const int lr = lane >> 2, lc = lane & 3;
        const int kk = k8 * 8 + lc, nn = n8 * 8 + lr;
        uint2 t;
        t.x = f32_to_tf32(W[(size_t)kk * HID + nn]);
        t.y = f32_to_tf32(W[(size_t)(kk + 4) * HID + nn]);
        ((uint2*)g_wc)[(size_t)which * NB_LANES + gg] = t;
    }
}

// ---------------------------------------------------------------------------
// QKV projection (exact R12): CTA 128x128, BK=32, 8 warps (2m x 4n, 64x32),
// cp.async 3-stage, 2 CTAs/SM.
// ---------------------------------------------------------------------------
#define NCH 32
#define A_TILE_B 16384
#define B_TILE_B 16384
#define STG_B (A_TILE_B + B_TILE_B)
#define QKV_SMEM (3 * STG_B)

__global__ __launch_bounds__(256, 2) void qkv_mma(
    const float* __restrict__ bq, const float* __restrict__ bk, const float* __restrict__ bv)
{
    extern __shared__ uint32_t smw[];
    const uint32_t sb = smem_u32(smw);

    const int which = blockIdx.z;
    const float* __restrict__ bias = (which == 0) ? bq : (which == 1) ? bk : bv;
    const size_t wcoff = (size_t)which * HID * HID * 4;

    const int m0 = blockIdx.y * 128;
    const int n0 = blockIdx.x * 128;
    const int m16_0 = blockIdx.y * 8;
    const int n8_0  = blockIdx.x * 16;

    const int tid  = threadIdx.x;
    const int wid  = tid >> 5;
    const int lane = tid & 31;
    const int lr = lane >> 2;
    const int lc = lane & 3;

    auto issue_stage = [&](int stg, int c) {
        const uint32_t ab = sb + (uint32_t)(stg * STG_B);
        const uint32_t bb = ab + A_TILE_B;
        const int k8_0 = c * 4;
        #pragma unroll
        for (int i = 0; i < 4; i++) {
            const int f = (tid >> 5) + i * 8;
            const size_t src = ((size_t)((m16_0 + (f >> 2)) * 128 + k8_0 + (f & 3))) * 512
                               + (tid & 31) * 16;
            CP_ASYNC16(ab + (uint32_t)(f * 512 + (tid & 31) * 16),
                       (const char*)g_xt + src);
        }
        #pragma unroll
        for (int i = 0; i < 4; i++) {
            const int ch = tid + i * 256;
            const int frag = ch >> 4, off = ch & 15;
            const size_t src = ((size_t)((n8_0 + (frag >> 2)) * 128 + k8_0 + (frag & 3))) * 256
                               + off * 16 + wcoff;
            CP_ASYNC16(bb + (uint32_t)(frag * 256 + off * 16),
                       (const char*)g_wc + src);
        }
    };

    float acc[4][4][4];
    #pragma unroll
    for (int mt = 0; mt < 4; mt++)
        #pragma unroll
        for (int nt = 0; nt < 4; nt++)
            #pragma unroll
            for (int r = 0; r < 4; r++) acc[mt][nt][r] = 0.0f;

    issue_stage(0, 0);   CP_COMMIT();
    issue_stage(1, 1);   CP_COMMIT();

    int stg = 0;
    for (int c = 0; c < NCH; c++) {
        CP_WAIT1();
        __syncthreads();

        if (c + 2 < NCH)
            issue_stage((stg + 2) % 3, c + 2);
        CP_COMMIT();

        const uint32_t* As = smw + stg * (STG_B / 4);
        const uint32_t* Bs = As + A_TILE_B / 4;

        #pragma unroll
        for (int kk8 = 0; kk8 < 4; kk8++) {
            uint2 bf[4];
            #pragma unroll
            for (int nt = 0; nt < 4; nt++) {
                const int slot = (((wid >> 1) * 4 + nt) * 4 + kk8);
                bf[nt] = *(const uint2*)(Bs + slot * 64 + lane * 2);
            }
            #pragma unroll
            for (int mt = 0; mt < 4; mt++) {
                const int slot = (((wid & 1) * 4 + mt) * 4 + kk8);
                const uint4 av = *(const uint4*)(As + slot * 128 + lane * 4);
                #pragma unroll
                for (int nt = 0; nt < 4; nt++)
                    mma_tf32_16x8x8(acc[mt][nt][0], acc[mt][nt][1],
                                    acc[mt][nt][2], acc[mt][nt][3],
                                    av.x, av.y, av.z, av.w, bf[nt].x, bf[nt].y);
            }
        }
        stg = (stg + 1) % 3;
    }

    const int wm = (wid & 1) * 64;
    const int wn = (wid >> 1) * 32;
    #pragma unroll
    for (int mt = 0; mt < 4; mt++) {
        #pragma unroll
        for (int nt = 0; nt < 4; nt++) {
            const int dd = wn + nt * 8 + 2 * lc;
            const int h  = (n0 + dd) >> 6;
            const int d  = dd & 63;
            const float bx = bias[n0 + dd];
            const float by = bias[n0 + dd + 1];
            #pragma unroll
            for (int half = 0; half < 2; half++) {
                const int m  = m0 + wm + mt * 16 + half * 8 + lr;
                const int b_ = m >> 10;
                const int s  = m & 1023;
                const float ox = acc[mt][nt][2 * half + 0] + bx;
                const float oy = acc[mt][nt][2 * half + 1] + by;
                if (which == 0) {
                    const size_t idx = (((size_t)(b_ * NH + h) * SEQ + s) << 6) + d;
                    *(float2*)&g_q[idx] = make_float2(ox, oy);
                } else if (which == 1) {
                    const size_t idx = (((size_t)(b_ * NH + h) * SEQ + s) << 6) + d;
                    *(float2*)&g_k[idx] = make_float2(ox, oy);
                } else {
                    const size_t fragbase =
                        (((size_t)(b_ * NH + h) * 128 + (s >> 3)) * 8 + (d >> 3)) * 64;
                    const int hw = (s >> 2) & 1;
                    g_v[fragbase + (((d & 7)    ) * 4 + (s & 3)) * 2 + hw] = f32_to_tf32(ox);
                    g_v[fragbase + (((d & 7) + 1) * 4 + (s & 3)) * 2 + hw] = f32_to_tf32(oy);
                }
            }
        }
    }
}

// ---------------------------------------------------------------------------
// RoPE. Q -> tf32 A-frag-major (g_q2); K -> tf32 B-frag pair-major (g_k2).
// ---------------------------------------------------------------------------
__global__ __launch_bounds__(256) void rope_kernel(const float* __restrict__ freqs)
{
    const int p  = blockIdx.x * 256 + threadIdx.x;
    const int d  = p & 31;
    const int s  = (p >> 5) & 1023;
    const int bh = p >> 15;
    const float f = freqs[s * 64 + d];
    const float sn = sinf(f), c = cosf(f);
    const size_t base = (((size_t)bh << 10) + s) * 64 + d;
    if (blockIdx.y == 0) {
        const float x1 = g_q[base];
        const float x2 = g_q[base + 32];
        const uint32_t v1 = f32_to_tf32(x1 * c - x2 * sn);
        const uint32_t v2 = f32_to_tf32(x2 * c + x1 * sn);
        const size_t fb = ((size_t)bh * 64 + (s >> 4)) * 8;
        const int lanew = ((s & 7) * 4 + (d & 3)) * 4 + ((s >> 3) & 1) + 2 * ((d >> 2) & 1);
        g_q2[(fb + (d >> 3)    ) * 128 + lanew] = v1;
        g_q2[(fb + (d >> 3) + 4) * 128 + lanew] = v2;
    } else {
        const float x1 = g_k[base];
        const float x2 = g_k[base + 32];
        const uint32_t v1 = f32_to_tf32(x1 * c - x2 * sn);
        const uint32_t v2 = f32_to_tf32(x2 * c + x1 * sn);
        const size_t slotbase = ((size_t)bh * 128 + (s >> 3)) * 8;
        const int lanepart = (s & 7) * 4 + (d & 3);
        const int halfw    = (d >> 2) & 1;
        g_k2[(slotbase + (d >> 3)    ) * 64 + lanepart * 2 + halfw] = v1;
        g_k2[(slotbase + (d >> 3) + 4) * 64 + lanepart * 2 + halfw] = v2;
    }
}

// ---------------------------------------------------------------------------
// Flash attention (R12 arithmetic, bit-exact): 1-term tf32, q-tile 64, 4 warps,
// Q via LDG.128 (A-frag-major), K/V fragment-major smem (LDS.64).
// CHANGE vs R12: unified KV double-buffer (one cp.async group per tile) —
// no mid-tile V wait; 2 syncs + 1 wait per tile. 2 CTAs/SM.
// ---------------------------------------------------------------------------
#define KSTR 68
#define KV_STG_W 8192                      // K tile 4096 w + V tile 4096 w (32KB)
#define PS_OFF (2 * KV_STG_W)              // 16384
#define MSK_OFF (PS_OFF + 64 * KSTR)       // 20736
#define ATTN_SMEM ((MSK_OFF + SEQ) * 4)    // 87040 bytes -> 2 CTAs/SM

__global__ __launch_bounds__(128, 2) void attn_mma(
    const float* __restrict__ mask, float* __restrict__ out)
{
    extern __shared__ uint32_t sm[];
    const uint32_t sb = smem_u32(sm);
    float*    Msk = (float*)(sm + MSK_OFF);
    uint32_t* Psb = sm + PS_OFF;

    const int q0 = blockIdx.x * 64;
    const int h  = blockIdx.y;
    const int b  = blockIdx.z;
    const int tid  = threadIdx.x;
    const int w    = tid >> 5;
    const int lane = tid & 31;
    const int lr = lane >> 2;
    const int lc = lane & 3;
    const int bh = b * NH + h;

    for (int i = tid; i < SEQ; i += 128) Msk[i] = mask[b * SEQ + i];

    // Q fragments: one LDG.128 per ds, loaded once (A-frag-major)
    uint32_t qh[8][4];
    {
        const uint32_t* qsrc = g_q2 + ((size_t)bh * 64 + (q0 >> 4) + w) * 1024;
        #pragma unroll
        for (int ds = 0; ds < 8; ds++) {
            const uint4 v = *(const uint4*)(qsrc + ds * 128 + lane * 4);
            qh[ds][0] = v.x; qh[ds][1] = v.y; qh[ds][2] = v.z; qh[ds][3] = v.w;
        }
    }
    __syncthreads();

    int nlive = 0;
    while (nlive < 16 && Msk[nlive * 64] >= -1e5f) nlive++;

    // stage both K and V tiles for k-tile index kti into buffer stg
    auto stage_kv = [&](int stg, int kti) {
        const uint32_t kb = sb + (uint32_t)(stg * KV_STG_W * 4);
        const uint32_t vb = kb + 4096 * 4;
        const char* ksrc = (const char*)g_k2 + (((size_t)bh * 128 + kti * 8) * 2048);
        const char* vsrc = (const char*)g_v  + (((size_t)bh * 128 + kti * 8) * 2048);
        #pragma unroll
        for (int j = 0; j < 8; j++) {
            const int off = (tid + j * 128) * 16;
            CP_ASYNC16(kb + (uint32_t)off, ksrc + off);
            CP_ASYNC16(vb + (uint32_t)off, vsrc + off);
        }
    };

    float m0 = -1e30f, m1 = -1e30f, l0 = 0.0f, l1 = 0.0f;
    float ctx[8][4];
    #pragma unroll
    for (int nt = 0; nt < 8; nt++)
        #pragma unroll
        for (int r = 0; r < 4; r++) ctx[nt][r] = 0.0f;

    stage_kv(0, 0);
    CP_COMMIT();                          // pending: [KV0]

    for (int kt = 0; kt < nlive; kt++) {
        const int kc0 = kt * 64;

        __syncthreads();                  // prior iter's reads of buf (kt+1)&1 done
        if (kt + 1 < nlive)
            stage_kv((kt + 1) & 1, kt + 1);
        CP_COMMIT();                      // +[KV(kt+1)] (possibly empty)

        CP_WAIT1();                       // KV(kt) complete
        __syncthreads();                  // cross-thread smem visibility

        const uint32_t* Ksb = sm + (kt & 1) * KV_STG_W;
        const uint32_t* Vsb = Ksb + 4096;

        // ---- S = Q K^T (1-term) ----
        float sa[8][4];
        #pragma unroll
        for (int nt = 0; nt < 8; nt++)
            #pragma unroll
            for (int r = 0; r < 4; r++) sa[nt][r] = 0.0f;

        #pragma unroll
        for (int ds = 0; ds < 8; ds++) {
            #pragma unroll
            for (int nt = 0; nt < 8; nt++) {
                const uint2 kv = *(const uint2*)(Ksb + (nt * 8 + ds) * 64 + lane * 2);
                mma_tf32_16x8x8(sa[nt][0], sa[nt][1], sa[nt][2], sa[nt][3],
                                qh[ds][0], qh[ds][1], qh[ds][2], qh[ds][3], kv.x, kv.y);
            }
        }

        // ---- scale + mask + online softmax ----
        float mx0 = -1e30f, mx1 = -1e30f;
        #pragma unroll
        for (int nt = 0; nt < 8; nt++) {
            const float mk0 = Msk[kc0 + nt * 8 + 2 * lc    ];
            const float mk1 = Msk[kc0 + nt * 8 + 2 * lc + 1];
            sa[nt][0] = fmaf(sa[nt][0], 0.125f, mk0);
            sa[nt][1] = fmaf(sa[nt][1], 0.125f, mk1);
            sa[nt][2] = fmaf(sa[nt][2], 0.125f, mk0);
            sa[nt][3] = fmaf(sa[nt][3], 0.125f, mk1);
            mx0 = fmaxf(mx0, fmaxf(sa[nt][0], sa[nt][1]));
            mx1 = fmaxf(mx1, fmaxf(sa[nt][2], sa[nt][3]));
        }
        mx0 = fmaxf(mx0, __shfl_xor_sync(0xffffffffu, mx0, 1));
        mx0 = fmaxf(mx0, __shfl_xor_sync(0xffffffffu, mx0, 2));
        mx1 = fmaxf(mx1, __shfl_xor_sync(0xffffffffu, mx1, 1));
        mx1 = fmaxf(mx1, __shfl_xor_sync(0xffffffffu, mx1, 2));

        const float mn0 = fmaxf(m0, mx0);
        const float mn1 = fmaxf(m1, mx1);
        const float cr0 = __expf(m0 - mn0);
        const float cr1 = __expf(m1 - mn1);
        l0 *= cr0; l1 *= cr1;
        m0 = mn0; m1 = mn1;

        float ps0 = 0.0f, ps1 = 0.0f;
        #pragma unroll
        for (int nt = 0; nt < 8; nt++) {
            ctx[nt][0] *= cr0; ctx[nt][1] *= cr0;
            ctx[nt][2] *= cr1; ctx[nt][3] *= cr1;
            sa[nt][0] = __expf(sa[nt][0] - mn0);
            sa[nt][1] = __expf(sa[nt][1] - mn0);
            sa[nt][2] = __expf(sa[nt][2] - mn1);
            sa[nt][3] = __expf(sa[nt][3] - mn1);
            ps0 += sa[nt][0] + sa[nt][1];
            ps1 += sa[nt][2] + sa[nt][3];
        }
        ps0 += __shfl_xor_sync(0xffffffffu, ps0, 1);
        ps0 += __shfl_xor_sync(0xffffffffu, ps0, 2);
        ps1 += __shfl_xor_sync(0xffffffffu, ps1, 1);
        ps1 += __shfl_xor_sync(0xffffffffu, ps1, 2);
        l0 += ps0; l1 += ps1;

        // store P as tf32 bits (warp-private rows)
        #pragma unroll
        for (int nt = 0; nt < 8; nt++) {
            uint2 u0, u1;
            u0.x = f32_to_tf32(sa[nt][0]); u0.y = f32_to_tf32(sa[nt][1]);
            u1.x = f32_to_tf32(sa[nt][2]); u1.y = f32_to_tf32(sa[nt][3]);
            *(uint2*)&Psb[(16 * w + lr    ) * KSTR + nt * 8 + 2 * lc] = u0;
            *(uint2*)&Psb[(16 * w + lr + 8) * KSTR + nt * 8 + 2 * lc] = u1;
        }
        __syncwarp();

        // ---- ctx += P V (1-term, V already resident — no wait) ----
        #pragma unroll
        for (int kk = 0; kk < 8; kk++) {
            uint32_t ah[4];
            ah[0] = Psb[(16 * w + lr    ) * KSTR + kk * 8 + lc    ];
            ah[1] = Psb[(16 * w + lr + 8) * KSTR + kk * 8 + lc    ];
            ah[2] = Psb[(16 * w + lr    ) * KSTR + kk * 8 + lc + 4];
            ah[3] = Psb[(16 * w + lr + 8) * KSTR + kk * 8 + lc + 4];
            #pragma unroll
            for (int nt = 0; nt < 8; nt++) {
                const uint2 vv = *(const uint2*)(Vsb + (kk * 8 + nt) * 64 + lane * 2);
                mma_tf32_16x8x8(ctx[nt][0], ctx[nt][1], ctx[nt][2], ctx[nt][3],
                                ah[0], ah[1], ah[2], ah[3], vv.x, vv.y);
            }
        }
    }

    const float inv0 = 1.0f / l0;
    const float inv1 = 1.0f / l1;
    const int row0 = q0 + 16 * w + lr;
    const int row1 = row0 + 8;
    #pragma unroll
    for (int nt = 0; nt < 8; nt++) {
        const int d = nt * 8 + 2 * lc;
        *(float2*)&out[(size_t)(b * SEQ + row0) * (NH * DH) + h * 64 + d] =
            make_float2(ctx[nt][0] * inv0, ctx[nt][1] * inv0);
        *(float2*)&out[(size_t)(b * SEQ + row1) * (NH * DH) + h * 64 + d] =
            make_float2(ctx[nt][2] * inv1, ctx[nt][3] * inv1);
    }
}

// ---------------------------------------------------------------------------
extern "C" void kernel_launch(void* const* d_in, const int* in_sizes, int n_in,
                              void* d_out, int out_size)
{
    const float* X     = (const float*)d_in[0];
    const float* mask  = (const float*)d_in[1];
    const float* freqs = (const float*)d_in[2];
    const float* Wq    = (const float*)d_in[3];
    const float* bq    = (const float*)d_in[4];
    const float* Wk    = (const float*)d_in[5];
    const float* bk    = (const float*)d_in[6];
    const float* Wv    = (const float*)d_in[7];
    const float* bv    = (const float*)d_in[8];
    float* out = (float*)d_out;

    cudaFuncSetAttribute(qkv_mma,  cudaFuncAttributeMaxDynamicSharedMemorySize, QKV_SMEM);
    cudaFuncSetAttribute(attn_mma, cudaFuncAttributeMaxDynamicSharedMemorySize, ATTN_SMEM);

    const int total = NA_LANES + 3 * NB_LANES;
    precvt<<<total / 256, 256>>>(X, Wq, Wk, Wv);

    dim3 gG(HID / 128, (BATCH * SEQ) / 128, 3);   // 8 x 32 x 3
    qkv_mma<<<gG, 256, QKV_SMEM>>>(bq, bk, bv);

    dim3 gR((BATCH * NH * SEQ * 32) / 256, 2);
    rope_kernel<<<gR, 256>>>(freqs);

    dim3 gA(SEQ / 64, NH, BATCH);                 // 16 x 16 x 4
    attn_mma<<<gA, 128, ATTN_SMEM>>>(mask, out);
}

// round 17
// speedup vs baseline: 1.0688x; 1.0443x over previous
#include <cuda_runtime.h>
#include <cuda_bf16.h>
#include <cstdint>

// Problem: B=4, S=1024, HID=1024, H=16, DH=64
// inputs: 0 hidden [4096,1024] f32, 1 mask [4,1024] f32, 2 freqs [1024,64] f32,
//         3 Wq, 4 bq, 5 Wk, 6 bk, 7 Wv, 8 bv
// output: ctx [4,1024,1024] f32

#define BATCH 4
#define SEQ   1024
#define HID   1024
#define NH    16
#define DH    64

// scratch (rope fused into qkv: no f32 Q/K intermediates)
__device__ uint32_t g_q2[BATCH*NH*SEQ*DH];   // tf32 bits, A-frag-major (roped)
__device__ uint32_t g_k2[BATCH*NH*SEQ*DH];   // tf32 bits, B-frag pair-major (roped)
__device__ uint32_t g_v [BATCH*NH*SEQ*DH];   // tf32 bits, B-frag pair-major
__device__ uint32_t g_xt[BATCH*SEQ*HID];     // X tf32 bits, A-fragment-major
__device__ uint32_t g_wc[3*HID*HID];         // W tf32 bits, B-fragment pair-major

__device__ __forceinline__ uint32_t f32_to_tf32(float x) {
    uint32_t u;
    asm("cvt.rna.tf32.f32 %0, %1;" : "=r"(u) : "f"(x));
    return u;
}

__device__ __forceinline__ void mma_tf32_16x8x8(
    float& c0, float& c1, float& c2, float& c3,
    uint32_t a0, uint32_t a1, uint32_t a2, uint32_t a3,
    uint32_t b0, uint32_t b1)
{
    asm volatile(
        "mma.sync.aligned.m16n8k8.row.col.f32.tf32.tf32.f32 "
        "{%0,%1,%2,%3}, {%4,%5,%6,%7}, {%8,%9}, {%0,%1,%2,%3};"
        : "+f"(c0), "+f"(c1), "+f"(c2), "+f"(c3)
        : "r"(a0), "r"(a1), "r"(a2), "r"(a3), "r"(b0), "r"(b1));
}

__device__ __forceinline__ uint32_t smem_u32(const void* p) {
    uint32_t a;
    asm("{ .reg .u64 t; cvta.to.shared.u64 t, %1; cvt.u32.u64 %0, t; }" : "=r"(a) : "l"(p));
    return a;
}

#define CP_ASYNC16(dst, src) \
    asm volatile("cp.async.cg.shared.global [%0], [%1], 16;" :: "r"(dst), "l"(src) : "memory")
#define CP_COMMIT() asm volatile("cp.async.commit_group;" ::: "memory")
#define CP_WAIT1()  asm volatile("cp.async.wait_group 1;" ::: "memory")
#define CP_WAIT2()  asm volatile("cp.async.wait_group 2;" ::: "memory")

// ---------------------------------------------------------------------------
// precvt: X -> g_xt (A-fragment-major), W -> g_wc (B-fragment pair-major).
// ---------------------------------------------------------------------------
#define NA_LANES (256*128*32)   // 1048576
#define NB_LANES (128*128*32)   // 524288

__global__ __launch_bounds__(256) void precvt(
    const float* __restrict__ X,
    const float* __restrict__ Wq, const float* __restrict__ Wk, const float* __restrict__ Wv)
{
    size_t g = (size_t)blockIdx.x * 256 + threadIdx.x;
    if (g < NA_LANES) {
        const int lane = (int)(g & 31);
        const int fA   = (int)(g >> 5);
        const int m16 = fA >> 7, k8 = fA & 127;
        const int lr = lane >> 2, lc = lane & 3;
        const int r0 = m16 * 16 + lr, c0 = k8 * 8 + lc;
        uint4 t;
        t.x = f32_to_tf32(X[(size_t)r0 * HID + c0]);
        t.y = f32_to_tf32(X[(size_t)(r0 + 8) * HID + c0]);
        t.z = f32_to_tf32(X[(size_t)r0 * HID + c0 + 4]);
        t.w = f32_to_tf32(X[(size_t)(r0 + 8) * HID + c0 + 4]);
        ((uint4*)g_xt)[g] = t;
    } else {
        g -= NA_LANES;
        const int which = (int)(g / NB_LANES);
        const size_t gg = g % NB_LANES;
        const float* __restrict__ W = (which == 0) ? Wq : (which == 1) ? Wk : Wv;
        const int lane = (int)(gg & 31);
        const int fB   = (int)(gg >> 5);
        const int n8 = fB >> 7, k8 = fB & 127;
        const int lr = lane >> 2, lc = lane & 3;
        const int kk = k8 * 8 + lc, nn = n8 * 8 + lr;
        uint2 t;
        t.x = f32_to_tf32(W[(size_t)kk * HID + nn]);
        t.y = f32_to_tf32(W[(size_t)(kk + 4) * HID + nn]);
        ((uint2*)g_wc)[(size_t)which * NB_LANES + gg] = t;
    }
}

// ---------------------------------------------------------------------------
// QKV projection (R12 main loop) + FUSED RoPE epilogue for Q/K:
// acc+bias staged to smem [128][132] f32 (stage buffers reused), then each
// thread ropes (s,d') pairs for both heads in the CTA tile and writes the
// fragment layouts directly. V epilogue unchanged (direct fragment write).
// ---------------------------------------------------------------------------
#define NCH 32
#define A_TILE_B 16384
#define B_TILE_B 16384
#define STG_B (A_TILE_B + B_TILE_B)
#define QKV_SMEM (3 * STG_B)            // 98304 B; epilogue reuses 128*132*4 = 67584 B
#define FT_STR 132

__global__ __launch_bounds__(256, 2) void qkv_mma(
    const float* __restrict__ freqs,
    const float* __restrict__ bq, const float* __restrict__ bk, const float* __restrict__ bv)
{
    extern __shared__ uint32_t smw[];
    const uint32_t sb = smem_u32(smw);

    const int which = blockIdx.z;
    const float* __restrict__ bias = (which == 0) ? bq : (which == 1) ? bk : bv;
    const size_t wcoff = (size_t)which * HID * HID * 4;

    const int m0 = blockIdx.y * 128;
    const int n0 = blockIdx.x * 128;
    const int m16_0 = blockIdx.y * 8;
    const int n8_0  = blockIdx.x * 16;

    const int tid  = threadIdx.x;
    const int wid  = tid >> 5;
    const int lane = tid & 31;
    const int lr = lane >> 2;
    const int lc = lane & 3;

    auto issue_stage = [&](int stg, int c) {
        const uint32_t ab = sb + (uint32_t)(stg * STG_B);
        const uint32_t bb = ab + A_TILE_B;
        const int k8_0 = c * 4;
        #pragma unroll
        for (int i = 0; i < 4; i++) {
            const int f = (tid >> 5) + i * 8;
            const size_t src = ((size_t)((m16_0 + (f >> 2)) * 128 + k8_0 + (f & 3))) * 512
                               + (tid & 31) * 16;
            CP_ASYNC16(ab + (uint32_t)(f * 512 + (tid & 31) * 16),
                       (const char*)g_xt + src);
        }
        #pragma unroll
        for (int i = 0; i < 4; i++) {
            const int ch = tid + i * 256;
            const int frag = ch >> 4, off = ch & 15;
            const size_t src = ((size_t)((n8_0 + (frag >> 2)) * 128 + k8_0 + (frag & 3))) * 256
                               + off * 16 + wcoff;
            CP_ASYNC16(bb + (uint32_t)(frag * 256 + off * 16),
                       (const char*)g_wc + src);
        }
    };

    float acc[4][4][4];
    #pragma unroll
    for (int mt = 0; mt < 4; mt++)
        #pragma unroll
        for (int nt = 0; nt < 4; nt++)
            #pragma unroll
            for (int r = 0; r < 4; r++) acc[mt][nt][r] = 0.0f;

    issue_stage(0, 0);   CP_COMMIT();
    issue_stage(1, 1);   CP_COMMIT();

    int stg = 0;
    for (int c = 0; c < NCH; c++) {
        CP_WAIT1();
        __syncthreads();

        if (c + 2 < NCH)
            issue_stage((stg + 2) % 3, c + 2);
        CP_COMMIT();

        const uint32_t* As = smw + stg * (STG_B / 4);
        const uint32_t* Bs = As + A_TILE_B / 4;

        #pragma unroll
        for (int kk8 = 0; kk8 < 4; kk8++) {
            uint2 bf[4];
            #pragma unroll
            for (int nt = 0; nt < 4; nt++) {
                const int slot = (((wid >> 1) * 4 + nt) * 4 + kk8);
                bf[nt] = *(const uint2*)(Bs + slot * 64 + lane * 2);
            }
            #pragma unroll
            for (int mt = 0; mt < 4; mt++) {
                const int slot = (((wid & 1) * 4 + mt) * 4 + kk8);
                const uint4 av = *(const uint4*)(As + slot * 128 + lane * 4);
                #pragma unroll
                for (int nt = 0; nt < 4; nt++)
                    mma_tf32_16x8x8(acc[mt][nt][0], acc[mt][nt][1],
                                    acc[mt][nt][2], acc[mt][nt][3],
                                    av.x, av.y, av.z, av.w, bf[nt].x, bf[nt].y);
            }
        }
        stg = (stg + 1) % 3;
    }

    const int wm = (wid & 1) * 64;
    const int wn = (wid >> 1) * 32;

    if (which == 2) {
        // V: bias + direct B-fragment pair-major write (unchanged from R12)
        #pragma unroll
        for (int mt = 0; mt < 4; mt++) {
            #pragma unroll
            for (int nt = 0; nt < 4; nt++) {
                const int dd = wn + nt * 8 + 2 * lc;
                const int h  = (n0 + dd) >> 6;
                const int d  = dd & 63;
                const float bx = bias[n0 + dd];
                const float by = bias[n0 + dd + 1];
                #pragma unroll
                for (int half = 0; half < 2; half++) {
                    const int m  = m0 + wm + mt * 16 + half * 8 + lr;
                    const int b_ = m >> 10;
                    const int s  = m & 1023;
                    const float ox = acc[mt][nt][2 * half + 0] + bx;
                    const float oy = acc[mt][nt][2 * half + 1] + by;
                    const size_t fragbase =
                        (((size_t)(b_ * NH + h) * 128 + (s >> 3)) * 8 + (d >> 3)) * 64;
                    const int hw = (s >> 2) & 1;
                    g_v[fragbase + (((d & 7)    ) * 4 + (s & 3)) * 2 + hw] = f32_to_tf32(ox);
                    g_v[fragbase + (((d & 7) + 1) * 4 + (s & 3)) * 2 + hw] = f32_to_tf32(oy);
                }
            }
        }
    } else {
        // Q/K: stage biased tile to smem, then fused RoPE + fragment write.
        __syncthreads();   // main-loop smem reads done before reuse
        float* ft = (float*)smw;
        #pragma unroll
        for (int mt = 0; mt < 4; mt++) {
            #pragma unroll
            for (int nt = 0; nt < 4; nt++) {
                const int dd = wn + nt * 8 + 2 * lc;
                const float bx = bias[n0 + dd];
                const float by = bias[n0 + dd + 1];
                #pragma unroll
                for (int half = 0; half < 2; half++) {
                    const int ml = wm + mt * 16 + half * 8 + lr;
                    *(float2*)&ft[ml * FT_STR + dd] =
                        make_float2(acc[mt][nt][2 * half + 0] + bx,
                                    acc[mt][nt][2 * half + 1] + by);
                }
            }
        }
        __syncthreads();

        const int ml = tid >> 1;              // local row 0..127
        const int m  = m0 + ml;
        const int b_ = m >> 10;
        const int s  = m & 1023;
        const int db = (tid & 1) * 16;        // d' base (0 or 16)
        const int h0 = n0 >> 6;               // first head in tile

        #pragma unroll
        for (int j = 0; j < 16; j++) {
            const int dp = db + j;            // d' in [0,32)
            const float f = freqs[s * 64 + dp];
            const float sn = sinf(f), cc = cosf(f);
            #pragma unroll
            for (int hh = 0; hh < 2; hh++) {
                const int bh = b_ * NH + h0 + hh;
                const float x1 = ft[ml * FT_STR + hh * 64 + dp];
                const float x2 = ft[ml * FT_STR + hh * 64 + dp + 32];
                const uint32_t v1 = f32_to_tf32(x1 * cc - x2 * sn);   // (s, dp)
                const uint32_t v2 = f32_to_tf32(x2 * cc + x1 * sn);   // (s, dp+32)
                if (which == 0) {
                    const size_t fb = ((size_t)bh * 64 + (s >> 4)) * 8;
                    const int lanew = ((s & 7) * 4 + (dp & 3)) * 4
                                      + ((s >> 3) & 1) + 2 * ((dp >> 2) & 1);
                    g_q2[(fb + (dp >> 3)    ) * 128 + lanew] = v1;
                    g_q2[(fb + (dp >> 3) + 4) * 128 + lanew] = v2;
                } else {
                    const size_t slotbase = ((size_t)bh * 128 + (s >> 3)) * 8;
                    const int lanepart = (s & 7) * 4 + (dp & 3);
                    const int halfw    = (dp >> 2) & 1;
                    g_k2[(slotbase + (dp >> 3)    ) * 64 + lanepart * 2 + halfw] = v1;
                    g_k2[(slotbase + (dp >> 3) + 4) * 64 + lanepart * 2 + halfw] = v2;
                }
            }
        }
    }
}

// ---------------------------------------------------------------------------
// Flash attention (exact R12): 1-term tf32, q-tile 64, 4 warps,
// Q via LDG.128 (A-frag-major), K/V fragment-major smem (LDS.64),
// K double-buffered + V single-buffered cp.async, 3 CTAs/SM.
// ---------------------------------------------------------------------------
#define KSTR 68
#define KTILE_W 4096
#define K0_OFF 0
#define K1_OFF KTILE_W
#define V_OFF  (2 * KTILE_W)
#define PS_OFF (V_OFF + KTILE_W)
#define MSK_OFF (PS_OFF + 64 * KSTR)
#define ATTN_SMEM ((MSK_OFF + SEQ) * 4)    // 70656 -> 3 CTAs/SM

__global__ __launch_bounds__(128, 3) void attn_mma(
    const float* __restrict__ mask, float* __restrict__ out)
{
    extern __shared__ uint32_t sm[];
    const uint32_t sb = smem_u32(sm);
    float*    Msk = (float*)(sm + MSK_OFF);
    uint32_t* Psb = sm + PS_OFF;

    const int q0 = blockIdx.x * 64;
    const int h  = blockIdx.y;
    const int b  = blockIdx.z;
    const int tid  = threadIdx.x;
    const int w    = tid >> 5;
    const int lane = tid & 31;
    const int lr = lane >> 2;
    const int lc = lane & 3;
    const int bh = b * NH + h;

    for (int i = tid; i < SEQ; i += 128) Msk[i] = mask[b * SEQ + i];

    uint32_t qh[8][4];
    {
        const uint32_t* qsrc = g_q2 + ((size_t)bh * 64 + (q0 >> 4) + w) * 1024;
        #pragma unroll
        for (int ds = 0; ds < 8; ds++) {
            const uint4 v = *(const uint4*)(qsrc + ds * 128 + lane * 4);
            qh[ds][0] = v.x; qh[ds][1] = v.y; qh[ds][2] = v.z; qh[ds][3] = v.w;
        }
    }
    __syncthreads();

    int nlive = 0;
    while (nlive < 16 && Msk[nlive * 64] >= -1e5f) nlive++;

    auto stage_k = [&](int stg, int kc0) {
        const uint32_t kb = sb + (uint32_t)((stg ? K1_OFF : K0_OFF) * 4);
        const char* src = (const char*)g_k2 + (((size_t)bh * 128 + (kc0 >> 3)) * 2048);
        #pragma unroll
        for (int j = 0; j < 8; j++) {
            const int off = (tid + j * 128) * 16;
            CP_ASYNC16(kb + (uint32_t)off, src + off);
        }
    };
    auto stage_v = [&](int kc0) {
        const uint32_t vb = sb + (uint32_t)(V_OFF * 4);
        const char* src = (const char*)g_v + (((size_t)bh * 128 + (kc0 >> 3)) * 2048);
        #pragma unroll
        for (int j = 0; j < 8; j++) {
            const int off = (tid + j * 128) * 16;
            CP_ASYNC16(vb + (uint32_t)off, src + off);
        }
    };

    float m0 = -1e30f, m1 = -1e30f, l0 = 0.0f, l1 = 0.0f;
    float ctx[8][4];
    #pragma unroll
    for (int nt = 0; nt < 8; nt++)
        #pragma unroll
        for (int r = 0; r < 4; r++) ctx[nt][r] = 0.0f;

    stage_k(0, 0);
    CP_COMMIT();

    for (int kt = 0; kt < nlive; kt++) {
        const int kc0 = kt * 64;

        stage_v(kc0);
        CP_COMMIT();
        if (kt + 1 < nlive)
            stage_k((kt + 1) & 1, kc0 + 64);
        CP_COMMIT();

        CP_WAIT2();
        __syncthreads();

        const uint32_t* Ksb = sm + ((kt & 1) ? K1_OFF : K0_OFF);

        float sa[8][4];
        #pragma unroll
        for (int nt = 0; nt < 8; nt++)
            #pragma unroll
            for (int r = 0; r < 4; r++) sa[nt][r] = 0.0f;

        #pragma unroll
        for (int ds = 0; ds < 8; ds++) {
            #pragma unroll
            for (int nt = 0; nt < 8; nt++) {
                const uint2 kv = *(const uint2*)(Ksb + (nt * 8 + ds) * 64 + lane * 2);
                mma_tf32_16x8x8(sa[nt][0], sa[nt][1], sa[nt][2], sa[nt][3],
                                qh[ds][0], qh[ds][1], qh[ds][2], qh[ds][3], kv.x, kv.y);
            }
        }

        float mx0 = -1e30f, mx1 = -1e30f;
        #pragma unroll
        for (int nt = 0; nt < 8; nt++) {
            const float mk0 = Msk[kc0 + nt * 8 + 2 * lc    ];
            const float mk1 = Msk[kc0 + nt * 8 + 2 * lc + 1];
            sa[nt][0] = fmaf(sa[nt][0], 0.125f, mk0);
            sa[nt][1] = fmaf(sa[nt][1], 0.125f, mk1);
            sa[nt][2] = fmaf(sa[nt][2], 0.125f, mk0);
            sa[nt][3] = fmaf(sa[nt][3], 0.125f, mk1);
            mx0 = fmaxf(mx0, fmaxf(sa[nt][0], sa[nt][1]));
            mx1 = fmaxf(mx1, fmaxf(sa[nt][2], sa[nt][3]));
        }
        mx0 = fmaxf(mx0, __shfl_xor_sync(0xffffffffu, mx0, 1));
        mx0 = fmaxf(mx0, __shfl_xor_sync(0xffffffffu, mx0, 2));
        mx1 = fmaxf(mx1, __shfl_xor_sync(0xffffffffu, mx1, 1));
        mx1 = fmaxf(mx1, __shfl_xor_sync(0xffffffffu, mx1, 2));

        const float mn0 = fmaxf(m0, mx0);
        const float mn1 = fmaxf(m1, mx1);
        const float cr0 = __expf(m0 - mn0);
        const float cr1 = __expf(m1 - mn1);
        l0 *= cr0; l1 *= cr1;
        m0 = mn0; m1 = mn1;

        float ps0 = 0.0f, ps1 = 0.0f;
        #pragma unroll
        for (int nt = 0; nt < 8; nt++) {
            ctx[nt][0] *= cr0; ctx[nt][1] *= cr0;
            ctx[nt][2] *= cr1; ctx[nt][3] *= cr1;
            sa[nt][0] = __expf(sa[nt][0] - mn0);
            sa[nt][1] = __expf(sa[nt][1] - mn0);
            sa[nt][2] = __expf(sa[nt][2] - mn1);
            sa[nt][3] = __expf(sa[nt][3] - mn1);
            ps0 += sa[nt][0] + sa[nt][1];
            ps1 += sa[nt][2] + sa[nt][3];
        }
        ps0 += __shfl_xor_sync(0xffffffffu, ps0, 1);
        ps0 += __shfl_xor_sync(0xffffffffu, ps0, 2);
        ps1 += __shfl_xor_sync(0xffffffffu, ps1, 1);
        ps1 += __shfl_xor_sync(0xffffffffu, ps1, 2);
        l0 += ps0; l1 += ps1;

        #pragma unroll
        for (int nt = 0; nt < 8; nt++) {
            uint2 u0, u1;
            u0.x = f32_to_tf32(sa[nt][0]); u0.y = f32_to_tf32(sa[nt][1]);
            u1.x = f32_to_tf32(sa[nt][2]); u1.y = f32_to_tf32(sa[nt][3]);
            *(uint2*)&Psb[(16 * w + lr    ) * KSTR + nt * 8 + 2 * lc] = u0;
            *(uint2*)&Psb[(16 * w + lr + 8) * KSTR + nt * 8 + 2 * lc] = u1;
        }
        __syncwarp();

        CP_WAIT1();
        __syncthreads();

        const uint32_t* Vsb = sm + V_OFF;

        #pragma unroll
        for (int kk = 0; kk < 8; kk++) {
            uint32_t ah[4];
            ah[0] = Psb[(16 * w + lr    ) * KSTR + kk * 8 + lc    ];
            ah[1] = Psb[(16 * w + lr + 8) * KSTR + kk * 8 + lc    ];
            ah[2] = Psb[(16 * w + lr    ) * KSTR + kk * 8 + lc + 4];
            ah[3] = Psb[(16 * w + lr + 8) * KSTR + kk * 8 + lc + 4];
            #pragma unroll
            for (int nt = 0; nt < 8; nt++) {
                const uint2 vv = *(const uint2*)(Vsb + (kk * 8 + nt) * 64 + lane * 2);
                mma_tf32_16x8x8(ctx[nt][0], ctx[nt][1], ctx[nt][2], ctx[nt][3],
                                ah[0], ah[1], ah[2], ah[3], vv.x, vv.y);
            }
        }

        __syncthreads();
    }

    const float inv0 = 1.0f / l0;
    const float inv1 = 1.0f / l1;
    const int row0 = q0 + 16 * w + lr;
    const int row1 = row0 + 8;
    #pragma unroll
    for (int nt = 0; nt < 8; nt++) {
        const int d = nt * 8 + 2 * lc;
        *(float2*)&out[(size_t)(b * SEQ + row0) * (NH * DH) + h * 64 + d] =
            make_float2(ctx[nt][0] * inv0, ctx[nt][1] * inv0);
        *(float2*)&out[(size_t)(b * SEQ + row1) * (NH * DH) + h * 64 + d] =
            make_float2(ctx[nt][2] * inv1, ctx[nt][3] * inv1);
    }
}

// ---------------------------------------------------------------------------
extern "C" void kernel_launch(void* const* d_in, const int* in_sizes, int n_in,
                              void* d_out, int out_size)
{
    const float* X     = (const float*)d_in[0];
    const float* mask  = (const float*)d_in[1];
    const float* freqs = (const float*)d_in[2];
    const float* Wq    = (const float*)d_in[3];
    const float* bq    = (const float*)d_in[4];
    const float* Wk    = (const float*)d_in[5];
    const float* bk    = (const float*)d_in[6];
    const float* Wv    = (const float*)d_in[7];
    const float* bv    = (const float*)d_in[8];
    float* out = (float*)d_out;

    cudaFuncSetAttribute(qkv_mma,  cudaFuncAttributeMaxDynamicSharedMemorySize, QKV_SMEM);
    cudaFuncSetAttribute(attn_mma, cudaFuncAttributeMaxDynamicSharedMemorySize, ATTN_SMEM);

    const int total = NA_LANES + 3 * NB_LANES;
    precvt<<<total / 256, 256>>>(X, Wq, Wk, Wv);

    dim3 gG(HID / 128, (BATCH * SEQ) / 128, 3);   // 8 x 32 x 3
    qkv_mma<<<gG, 256, QKV_SMEM>>>(freqs, bq, bk, bv);

    dim3 gA(SEQ / 64, NH, BATCH);                 // 16 x 16 x 4
    attn_mma<<<gA, 128, ATTN_SMEM>>>(mask, out);
}